// round 14
// baseline (speedup 1.0000x reference)
#include <cuda_runtime.h>
#include <cuda_bf16.h>
#include <math.h>
#include <stdint.h>

#define BB 8
#define NN 10000
#define FF 1024
#define ZZ 512
#define CC 4
#define ROWS (BB * NN)   // 80000 = 625 * 128

// ---------------- scratch (no allocations allowed) ----------------
__device__ __nv_bfloat16 g_bagsbf[(size_t)ROWS * FF];
__device__ __nv_bfloat16 g_emb[(size_t)ROWS * ZZ];
__device__ __nv_bfloat16 g_WencT[(size_t)ZZ * FF];  // [n][k]
__device__ __nv_bfloat16 g_WuT[(size_t)ZZ * ZZ];    // [n][k]
__device__ __nv_bfloat16 g_WvT[(size_t)ZZ * ZZ];    // [n][k]
__device__ float g_logits[BB * CC * NN];
__device__ float g_attn[BB * CC * NN];
__device__ float g_reps[BB * CC * ZZ];

// ---------------- helpers ----------------
__device__ __forceinline__ uint32_t s2u(const void* p) {
    uint32_t a;
    asm("{ .reg .u64 t; cvta.to.shared.u64 t, %1; cvt.u32.u64 %0, t; }"
        : "=r"(a) : "l"(p));
    return a;
}

__device__ __forceinline__ void mma_bf16(float d[4], const uint32_t a[4],
                                         const uint32_t b[2]) {
    asm volatile(
        "mma.sync.aligned.m16n8k16.row.col.f32.bf16.bf16.f32 "
        "{%0,%1,%2,%3}, {%4,%5,%6,%7}, {%8,%9}, {%0,%1,%2,%3};"
        : "+f"(d[0]), "+f"(d[1]), "+f"(d[2]), "+f"(d[3])
        : "r"(a[0]), "r"(a[1]), "r"(a[2]), "r"(a[3]), "r"(b[0]), "r"(b[1]));
}

__device__ __forceinline__ void ldsm4(uint32_t* r, uint32_t addr) {
    asm volatile("ldmatrix.sync.aligned.m8n8.x4.shared.b16 {%0,%1,%2,%3}, [%4];"
                 : "=r"(r[0]), "=r"(r[1]), "=r"(r[2]), "=r"(r[3]) : "r"(addr));
}

__device__ __forceinline__ void cp16(void* dst, const void* src) {
    uint32_t d = (uint32_t)__cvta_generic_to_shared(dst);
    asm volatile("cp.async.cg.shared.global [%0], [%1], 16;" ::"r"(d), "l"(src));
}
#define CP_COMMIT() asm volatile("cp.async.commit_group;" ::: "memory")

__device__ __forceinline__ float tanh_ap(float x) {
    float r;
    asm("tanh.approx.f32 %0, %1;" : "=f"(r) : "f"(x));
    return r;
}

// ---------------- prep kernels ----------------
__global__ void convert_bags_kernel(const float* __restrict__ in, size_t elem0) {
    size_t i = elem0 + ((size_t)blockIdx.x * 256 + threadIdx.x) * 8;
#pragma unroll
    for (int j = 0; j < 2; j++) {
        float4 v = *reinterpret_cast<const float4*>(in + i + 4 * j);
        __nv_bfloat162 lo = __float22bfloat162_rn(make_float2(v.x, v.y));
        __nv_bfloat162 hi = __float22bfloat162_rn(make_float2(v.z, v.w));
        uint2 u;
        u.x = *reinterpret_cast<uint32_t*>(&lo);
        u.y = *reinterpret_cast<uint32_t*>(&hi);
        *reinterpret_cast<uint2*>(&g_bagsbf[i + 4 * j]) = u;
    }
}

__global__ void prep_kernel(const float* __restrict__ We,
                            const float* __restrict__ Wu,
                            const float* __restrict__ Wv,
                            const float* __restrict__ b_attn) {
    int i = blockIdx.x * 256 + threadIdx.x;
    if (i < FF * ZZ) {
        int k = i / ZZ, n = i - k * ZZ;
        g_WencT[(size_t)n * FF + k] = __float2bfloat16(We[i]);
    }
    if (i < ZZ * ZZ) {
        int k = i / ZZ, n = i - k * ZZ;
        g_WuT[(size_t)n * ZZ + k] = __float2bfloat16(Wu[i]);
        g_WvT[(size_t)n * ZZ + k] = __float2bfloat16(Wv[i]);
    }
    if (i < BB * CC * NN) g_logits[i] = b_attn[(i / NN) & 3];
    if (i < BB * CC * ZZ) g_reps[i] = 0.f;
}

// ---------------- GEMM1: emb = relu(bagsbf @ W_enc + b_enc) -----------------
// (R10/R13 proven) 128x128 block, 4 warps (2x2) of 64x64, K-step 64, 2-stage,
// ldmatrix fragments, 2 CTAs/SM. row_blk0 = M-block offset for sliced launch.
#define LDK 72
#define G1_TILE (128 * LDK)
#define G1_STAGE (2 * G1_TILE)
#define G1_SMEM (2 * G1_STAGE * 2)   // 73728 bytes

__device__ __forceinline__ void g1_stage(__nv_bfloat16* sm, int slot, int kb,
                                         int bm, int bn, int tid) {
    __nv_bfloat16* As = sm + slot * G1_STAGE;
    __nv_bfloat16* Bs = As + G1_TILE;
#pragma unroll
    for (int j = 0; j < 8; j++) {
        int p = tid + j * 128;
        int r = p >> 3, ch = p & 7;
        cp16(&As[r * LDK + ch * 8], &g_bagsbf[(size_t)(bm + r) * FF + kb + ch * 8]);
        cp16(&Bs[r * LDK + ch * 8], &g_WencT[(size_t)(bn + r) * FF + kb + ch * 8]);
    }
}

__global__ __launch_bounds__(128, 2)
void gemm1_kernel(const float* __restrict__ bias, int row_blk0) {
    extern __shared__ __nv_bfloat16 sm[];
    __shared__ float s_bias[128];

    const int tid = threadIdx.x, wid = tid >> 5, lane = tid & 31;
    const int wm = wid >> 1, wn = wid & 1, g = lane >> 2, tg = lane & 3;
    const int lr = lane & 7, lm = lane >> 3;
    const int bm = (row_blk0 + blockIdx.y) * 128, bn = blockIdx.x * 128;
    const uint32_t smb = s2u(sm);

    s_bias[tid] = bias[bn + tid];

    const int a_rb = wm * 64 + lr + ((lm & 1) << 3);
    const int a_kc = (lm >> 1) << 3;
    const int b_rb = wn * 64 + lr + ((lm >> 1) << 3);
    const int b_kc = (lm & 1) << 3;

    float acc[4][8][4];
#pragma unroll
    for (int mt = 0; mt < 4; mt++)
#pragma unroll
        for (int nt = 0; nt < 8; nt++)
#pragma unroll
            for (int i = 0; i < 4; i++) acc[mt][nt][i] = 0.f;

#pragma unroll
    for (int s = 0; s < 2; s++) {
        g1_stage(sm, s, s * 64, bm, bn, tid);
        CP_COMMIT();
    }

    for (int c = 0; c < 16; c++) {                 // 16 chunks of K=64
        asm volatile("cp.async.wait_group 1;" ::: "memory");
        __syncthreads();
        const uint32_t sA = smb + (uint32_t)(c & 1) * G1_STAGE * 2;
        const uint32_t sB = sA + G1_TILE * 2;
#pragma unroll
        for (int kk = 0; kk < 64; kk += 16) {
            uint32_t afrag[4][4], bfrag[8][2];
#pragma unroll
            for (int mt = 0; mt < 4; mt++)
                ldsm4(afrag[mt], sA + ((a_rb + mt * 16) * LDK + kk + a_kc) * 2);
#pragma unroll
            for (int np = 0; np < 4; np++) {
                uint32_t t[4];
                ldsm4(t, sB + ((b_rb + np * 16) * LDK + kk + b_kc) * 2);
                bfrag[2 * np][0] = t[0]; bfrag[2 * np][1] = t[1];
                bfrag[2 * np + 1][0] = t[2]; bfrag[2 * np + 1][1] = t[3];
            }
#pragma unroll
            for (int mt = 0; mt < 4; mt++)
#pragma unroll
                for (int nt = 0; nt < 8; nt++)
                    mma_bf16(acc[mt][nt], afrag[mt], bfrag[nt]);
        }
        __syncthreads();
        if (c + 2 < 16) g1_stage(sm, c & 1, (c + 2) * 64, bm, bn, tid);
        CP_COMMIT();
    }

    // epilogue: bias + relu -> bf16
#pragma unroll
    for (int mt = 0; mt < 4; mt++) {
#pragma unroll
        for (int nt = 0; nt < 8; nt++) {
            int row0 = bm + wm * 64 + mt * 16 + g;
            int col = wn * 64 + nt * 8 + 2 * tg;
            float b0 = s_bias[col], b1 = s_bias[col + 1];
            float x0 = fmaxf(acc[mt][nt][0] + b0, 0.f);
            float x1 = fmaxf(acc[mt][nt][1] + b1, 0.f);
            float x2 = fmaxf(acc[mt][nt][2] + b0, 0.f);
            float x3 = fmaxf(acc[mt][nt][3] + b1, 0.f);
            *reinterpret_cast<__nv_bfloat162*>(&g_emb[(size_t)row0 * ZZ + bn + col]) =
                __float22bfloat162_rn(make_float2(x0, x1));
            *reinterpret_cast<__nv_bfloat162*>(&g_emb[(size_t)(row0 + 8) * ZZ + bn + col]) =
                __float22bfloat162_rn(make_float2(x2, x3));
        }
    }
}

// ---------------- fused u/v GEMM + gated + attention logits -----------------
// (R10/R13 proven) 128x128 block, 512 threads, 16 warps (4m x 4n) of 32x32
// DUAL tiles, K-step 32, 3 stages, ldmatrix fragments.
#define LDA 40
#define FU_TILE (128 * LDA)
#define FU_STAGE (3 * FU_TILE)
#define FU_SMEM (3 * FU_STAGE * 2)   // 92160 bytes

__device__ __forceinline__ void fu_stage(__nv_bfloat16* sm, int s, int bm,
                                         int bn, int kb, int tid) {
    __nv_bfloat16* As = sm + s * FU_STAGE;
    __nv_bfloat16* Bu = As + FU_TILE;
    __nv_bfloat16* Bv = Bu + FU_TILE;
    int r = tid >> 2, ch = tid & 3;
    cp16(&As[r * LDA + ch * 8], &g_emb[(size_t)(bm + r) * ZZ + kb + ch * 8]);
    cp16(&Bu[r * LDA + ch * 8], &g_WuT[(size_t)(bn + r) * ZZ + kb + ch * 8]);
    cp16(&Bv[r * LDA + ch * 8], &g_WvT[(size_t)(bn + r) * ZZ + kb + ch * 8]);
}

__global__ __launch_bounds__(512, 1)
void fused_uv_kernel(const float* __restrict__ bu_g,
                     const float* __restrict__ bv_g,
                     const float* __restrict__ Wa_g) {
    extern __shared__ __nv_bfloat16 sm[];
    __shared__ float sBu[128], sBv[128], sWa[CC * 128];

    const int tid = threadIdx.x, wid = tid >> 5, lane = tid & 31;
    const int wm = wid >> 2, wn = wid & 3, g = lane >> 2, tg = lane & 3;
    const int lr = lane & 7, lm = lane >> 3;
    const int bm = blockIdx.y * 128, bn = blockIdx.x * 128;
    const uint32_t smb = s2u(sm);

    if (tid < 128) {
        sBu[tid] = bu_g[bn + tid];
        sBv[tid] = bv_g[bn + tid];
    }
    sWa[tid] = Wa_g[(tid >> 7) * ZZ + bn + (tid & 127)];

    const int a_rb = wm * 32 + lr + ((lm & 1) << 3);
    const int a_kc = (lm >> 1) << 3;
    const int b_rb = wn * 32 + lr + ((lm >> 1) << 3);
    const int b_kc = (lm & 1) << 3;

    float accu[2][4][4], accv[2][4][4];
#pragma unroll
    for (int mt = 0; mt < 2; mt++)
#pragma unroll
        for (int nt = 0; nt < 4; nt++)
#pragma unroll
            for (int i = 0; i < 4; i++) { accu[mt][nt][i] = 0.f; accv[mt][nt][i] = 0.f; }

#pragma unroll
    for (int s = 0; s < 3; s++) {
        fu_stage(sm, s, bm, bn, s * 32, tid);
        CP_COMMIT();
    }

    for (int ks = 0; ks < 16; ks++) {
        asm volatile("cp.async.wait_group 2;" ::: "memory");
        __syncthreads();
        const uint32_t sA = smb + (uint32_t)(ks % 3) * FU_STAGE * 2;
        const uint32_t sU = sA + FU_TILE * 2;
        const uint32_t sV = sU + FU_TILE * 2;
#pragma unroll
        for (int kk = 0; kk < 32; kk += 16) {
            uint32_t a[2][4], bu[4][2], bv[4][2];
#pragma unroll
            for (int mt = 0; mt < 2; mt++)
                ldsm4(a[mt], sA + ((a_rb + mt * 16) * LDA + kk + a_kc) * 2);
#pragma unroll
            for (int np = 0; np < 2; np++) {
                uint32_t t[4];
                ldsm4(t, sU + ((b_rb + np * 16) * LDA + kk + b_kc) * 2);
                bu[2 * np][0] = t[0]; bu[2 * np][1] = t[1];
                bu[2 * np + 1][0] = t[2]; bu[2 * np + 1][1] = t[3];
                ldsm4(t, sV + ((b_rb + np * 16) * LDA + kk + b_kc) * 2);
                bv[2 * np][0] = t[0]; bv[2 * np][1] = t[1];
                bv[2 * np + 1][0] = t[2]; bv[2 * np + 1][1] = t[3];
            }
#pragma unroll
            for (int mt = 0; mt < 2; mt++)
#pragma unroll
                for (int nt = 0; nt < 4; nt++) {
                    mma_bf16(accu[mt][nt], a[mt], bu[nt]);
                    mma_bf16(accv[mt][nt], a[mt], bv[nt]);
                }
        }
        __syncthreads();
        if (ks + 3 < 16) fu_stage(sm, ks % 3, bm, bn, (ks + 3) * 32, tid);
        CP_COMMIT();
    }

    // epilogue: gated = sigmoid(u)*tanh(v); per-class dot -> logits
#pragma unroll
    for (int mt = 0; mt < 2; mt++) {
        float p0[CC] = {0.f, 0.f, 0.f, 0.f};
        float p1[CC] = {0.f, 0.f, 0.f, 0.f};
#pragma unroll
        for (int nt = 0; nt < 4; nt++) {
            int zl = wn * 32 + nt * 8 + 2 * tg;
            float bu0 = sBu[zl], bu1 = sBu[zl + 1];
            float bv0 = sBv[zl], bv1 = sBv[zl + 1];
            float u00 = 0.5f * tanh_ap(0.5f * (accu[mt][nt][0] + bu0)) + 0.5f;
            float u01 = 0.5f * tanh_ap(0.5f * (accu[mt][nt][1] + bu1)) + 0.5f;
            float u10 = 0.5f * tanh_ap(0.5f * (accu[mt][nt][2] + bu0)) + 0.5f;
            float u11 = 0.5f * tanh_ap(0.5f * (accu[mt][nt][3] + bu1)) + 0.5f;
            float g00 = u00 * tanh_ap(accv[mt][nt][0] + bv0);
            float g01 = u01 * tanh_ap(accv[mt][nt][1] + bv1);
            float g10 = u10 * tanh_ap(accv[mt][nt][2] + bv0);
            float g11 = u11 * tanh_ap(accv[mt][nt][3] + bv1);
#pragma unroll
            for (int c = 0; c < CC; c++) {
                float wa0 = sWa[c * 128 + zl], wa1 = sWa[c * 128 + zl + 1];
                p0[c] += g00 * wa0 + g01 * wa1;
                p1[c] += g10 * wa0 + g11 * wa1;
            }
        }
#pragma unroll
        for (int c = 0; c < CC; c++) {
            p0[c] += __shfl_xor_sync(0xffffffffu, p0[c], 1);
            p0[c] += __shfl_xor_sync(0xffffffffu, p0[c], 2);
            p1[c] += __shfl_xor_sync(0xffffffffu, p1[c], 1);
            p1[c] += __shfl_xor_sync(0xffffffffu, p1[c], 2);
        }
        if (tg == 0) {
            int gr0 = bm + wm * 32 + mt * 16 + g;
            int gr1 = gr0 + 8;
            int b0i = gr0 / NN, n0i = gr0 - b0i * NN;
            int b1i = gr1 / NN, n1i = gr1 - b1i * NN;
#pragma unroll
            for (int c = 0; c < CC; c++) {
                atomicAdd(&g_logits[(b0i * CC + c) * NN + n0i], p0[c]);
                atomicAdd(&g_logits[(b1i * CC + c) * NN + n1i], p1[c]);
            }
        }
    }
}

// ---------------- softmax over N per (b,c) ----------------
__global__ __launch_bounds__(256) void softmax_kernel() {
    const int bc = blockIdx.x;
    const float* l = &g_logits[(size_t)bc * NN];
    float* a = &g_attn[(size_t)bc * NN];
    const int t = threadIdx.x;
    __shared__ float red[256];

    float m = -INFINITY;
    for (int n = t; n < NN; n += 256) m = fmaxf(m, l[n]);
    red[t] = m;
    __syncthreads();
    for (int s = 128; s > 0; s >>= 1) {
        if (t < s) red[t] = fmaxf(red[t], red[t + s]);
        __syncthreads();
    }
    m = red[0];
    __syncthreads();
    float sum = 0.f;
    for (int n = t; n < NN; n += 256) {
        float e = expf(l[n] - m);
        a[n] = e;
        sum += e;
    }
    red[t] = sum;
    __syncthreads();
    for (int s = 128; s > 0; s >>= 1) {
        if (t < s) red[t] += red[t + s];
        __syncthreads();
    }
    float inv = 1.f / red[0];
    for (int n = t; n < NN; n += 256) a[n] *= inv;
}

// ---------------- reps = sum_n attn[b,c,n] * emb[b,n,z] ----------------
#define NSPLIT 40
__global__ __launch_bounds__(256) void reps_kernel() {
    const int ns = blockIdx.x;
    const int b = blockIdx.y;
    const int z = 2 * threadIdx.x;
    const int n0 = ns * (NN / NSPLIT), n1 = n0 + (NN / NSPLIT);
    const __nv_bfloat16* e = &g_emb[(size_t)b * NN * ZZ];

    float a0[CC] = {0.f, 0.f, 0.f, 0.f};
    float a1[CC] = {0.f, 0.f, 0.f, 0.f};
#pragma unroll 2
    for (int n = n0; n < n1; n++) {
        __nv_bfloat162 ev = *reinterpret_cast<const __nv_bfloat162*>(&e[(size_t)n * ZZ + z]);
        float2 ef = __bfloat1622float2(ev);
#pragma unroll
        for (int c = 0; c < CC; c++) {
            float at = g_attn[(b * CC + c) * NN + n];
            a0[c] += at * ef.x;
            a1[c] += at * ef.y;
        }
    }
#pragma unroll
    for (int c = 0; c < CC; c++) {
        atomicAdd(&g_reps[(b * CC + c) * ZZ + z], a0[c]);
        atomicAdd(&g_reps[(b * CC + c) * ZZ + z + 1], a1[c]);
    }
}

// ---------------- scores ----------------
__global__ __launch_bounds__(1024)
void scores_kernel(const float* __restrict__ W_cls,
                   const float* __restrict__ b_cls, float* __restrict__ out) {
    const int w = threadIdx.x >> 5, lane = threadIdx.x & 31;
    const int b = w >> 2, c = w & 3;
    float s = 0.f;
    for (int z = lane; z < ZZ; z += 32)
        s += g_reps[(b * CC + c) * ZZ + z] * W_cls[c * ZZ + z];
#pragma unroll
    for (int o = 16; o > 0; o >>= 1) s += __shfl_xor_sync(0xffffffffu, s, o);
    if (lane == 0) out[b * CC + c] = s + b_cls[c];
}

// ---------------- launch ----------------
extern "C" void kernel_launch(void* const* d_in, const int* in_sizes, int n_in,
                              void* d_out, int out_size) {
    const float* bags   = (const float*)d_in[0];
    const float* W_enc  = (const float*)d_in[1];
    const float* b_enc  = (const float*)d_in[2];
    const float* W_u    = (const float*)d_in[3];
    const float* b_u    = (const float*)d_in[4];
    const float* W_v    = (const float*)d_in[5];
    const float* b_v    = (const float*)d_in[6];
    const float* W_attn = (const float*)d_in[7];
    const float* b_attn = (const float*)d_in[8];
    const float* W_cls  = (const float*)d_in[9];
    const float* b_cls  = (const float*)d_in[10];
    float* out = (float*)d_out;

    cudaFuncSetAttribute(gemm1_kernel, cudaFuncAttributeMaxDynamicSharedMemorySize, G1_SMEM);
    cudaFuncSetAttribute(fused_uv_kernel, cudaFuncAttributeMaxDynamicSharedMemorySize, FU_SMEM);

    // one-time stream/event creation (host resources, not device memory)
    static cudaStream_t sAux = nullptr;
    static cudaEvent_t eFork, eC1, eC2, eC3;
    if (!sAux) {
        cudaStreamCreateWithFlags(&sAux, cudaStreamNonBlocking);
        cudaEventCreateWithFlags(&eFork, cudaEventDisableTiming);
        cudaEventCreateWithFlags(&eC1, cudaEventDisableTiming);
        cudaEventCreateWithFlags(&eC2, cudaEventDisableTiming);
        cudaEventCreateWithFlags(&eC3, cudaEventDisableTiming);
    }

    // M-block slices: 625 = 208 + 208 + 209
    const int blk0 = 208, blk1 = 208, blk2 = 209;
    const size_t e0 = 0;
    const size_t e1 = (size_t)blk0 * 128 * FF;                 // 27262976
    const size_t e2 = (size_t)(blk0 + blk1) * 128 * FF;        // 54525952
    const int cb0 = blk0 * 64, cb1 = blk1 * 64, cb2 = blk2 * 64;  // convert grids

    // fork aux stream off the capture (legacy) stream
    cudaEventRecord(eFork, 0);
    cudaStreamWaitEvent(sAux, eFork, 0);

    // aux: convert slices, signal after each
    convert_bags_kernel<<<cb0, 256, 0, sAux>>>(bags, e0);
    cudaEventRecord(eC1, sAux);
    convert_bags_kernel<<<cb1, 256, 0, sAux>>>(bags, e1);
    cudaEventRecord(eC2, sAux);
    convert_bags_kernel<<<cb2, 256, 0, sAux>>>(bags, e2);
    cudaEventRecord(eC3, sAux);

    // main: prep overlaps convert slice 1
    prep_kernel<<<(FF * ZZ + 255) / 256, 256>>>(W_enc, W_u, W_v, b_attn);

    // gemm1 slices, each gated on its convert slice (joins aux at eC3)
    cudaStreamWaitEvent(0, eC1, 0);
    gemm1_kernel<<<dim3(ZZ / 128, blk0), 128, G1_SMEM>>>(b_enc, 0);
    cudaStreamWaitEvent(0, eC2, 0);
    gemm1_kernel<<<dim3(ZZ / 128, blk1), 128, G1_SMEM>>>(b_enc, blk0);
    cudaStreamWaitEvent(0, eC3, 0);
    gemm1_kernel<<<dim3(ZZ / 128, blk2), 128, G1_SMEM>>>(b_enc, blk0 + blk1);

    // fused u/v GEMM + tail (proven R13 kernels)
    fused_uv_kernel<<<dim3(ZZ / 128, ROWS / 128), 512, FU_SMEM>>>(b_u, b_v, W_attn);
    softmax_kernel<<<BB * CC, 256>>>();
    reps_kernel<<<dim3(NSPLIT, BB), 256>>>();
    scores_kernel<<<1, 1024>>>(W_cls, b_cls, out);
}

// round 15
// speedup vs baseline: 1.0108x; 1.0108x over previous
#include <cuda_runtime.h>
#include <cuda_bf16.h>
#include <math.h>
#include <stdint.h>

#define BB 8
#define NN 10000
#define FF 1024
#define ZZ 512
#define CC 4
#define ROWS (BB * NN)   // 80000 = 625 * 128

// ---------------- scratch (no allocations allowed) ----------------
__device__ __nv_bfloat16 g_bagsbf[(size_t)ROWS * FF];
__device__ __nv_bfloat16 g_emb[(size_t)ROWS * ZZ];
__device__ __nv_bfloat16 g_WencT[(size_t)ZZ * FF];  // [n][k]
__device__ __nv_bfloat16 g_WuT[(size_t)ZZ * ZZ];    // [n][k]
__device__ __nv_bfloat16 g_WvT[(size_t)ZZ * ZZ];    // [n][k]
__device__ float g_logits[BB * CC * NN];
__device__ float g_attn[BB * CC * NN];
__device__ float g_reps[BB * CC * ZZ];

// ---------------- helpers ----------------
__device__ __forceinline__ uint32_t s2u(const void* p) {
    uint32_t a;
    asm("{ .reg .u64 t; cvta.to.shared.u64 t, %1; cvt.u32.u64 %0, t; }"
        : "=r"(a) : "l"(p));
    return a;
}

__device__ __forceinline__ void mma_bf16(float d[4], const uint32_t a[4],
                                         const uint32_t b[2]) {
    asm volatile(
        "mma.sync.aligned.m16n8k16.row.col.f32.bf16.bf16.f32 "
        "{%0,%1,%2,%3}, {%4,%5,%6,%7}, {%8,%9}, {%0,%1,%2,%3};"
        : "+f"(d[0]), "+f"(d[1]), "+f"(d[2]), "+f"(d[3])
        : "r"(a[0]), "r"(a[1]), "r"(a[2]), "r"(a[3]), "r"(b[0]), "r"(b[1]));
}

__device__ __forceinline__ void ldsm4(uint32_t* r, uint32_t addr) {
    asm volatile("ldmatrix.sync.aligned.m8n8.x4.shared.b16 {%0,%1,%2,%3}, [%4];"
                 : "=r"(r[0]), "=r"(r[1]), "=r"(r[2]), "=r"(r[3]) : "r"(addr));
}

__device__ __forceinline__ void cp16(void* dst, const void* src) {
    uint32_t d = (uint32_t)__cvta_generic_to_shared(dst);
    asm volatile("cp.async.cg.shared.global [%0], [%1], 16;" ::"r"(d), "l"(src));
}
#define CP_COMMIT() asm volatile("cp.async.commit_group;" ::: "memory")

__device__ __forceinline__ float tanh_ap(float x) {
    float r;
    asm("tanh.approx.f32 %0, %1;" : "=f"(r) : "f"(x));
    return r;
}

// ---------------- prep kernels ----------------
__global__ void convert_bags_kernel(const float* __restrict__ in) {
    size_t i = ((size_t)blockIdx.x * 256 + threadIdx.x) * 8;
#pragma unroll
    for (int j = 0; j < 2; j++) {
        float4 v = *reinterpret_cast<const float4*>(in + i + 4 * j);
        __nv_bfloat162 lo = __float22bfloat162_rn(make_float2(v.x, v.y));
        __nv_bfloat162 hi = __float22bfloat162_rn(make_float2(v.z, v.w));
        uint2 u;
        u.x = *reinterpret_cast<uint32_t*>(&lo);
        u.y = *reinterpret_cast<uint32_t*>(&hi);
        *reinterpret_cast<uint2*>(&g_bagsbf[i + 4 * j]) = u;
    }
}

__global__ void prep_kernel(const float* __restrict__ We,
                            const float* __restrict__ Wu,
                            const float* __restrict__ Wv,
                            const float* __restrict__ b_attn) {
    int i = blockIdx.x * 256 + threadIdx.x;
    if (i < FF * ZZ) {
        int k = i / ZZ, n = i - k * ZZ;
        g_WencT[(size_t)n * FF + k] = __float2bfloat16(We[i]);
    }
    if (i < ZZ * ZZ) {
        int k = i / ZZ, n = i - k * ZZ;
        g_WuT[(size_t)n * ZZ + k] = __float2bfloat16(Wu[i]);
        g_WvT[(size_t)n * ZZ + k] = __float2bfloat16(Wv[i]);
    }
    if (i < BB * CC * NN) g_logits[i] = b_attn[(i / NN) & 3];
    if (i < BB * CC * ZZ) g_reps[i] = 0.f;
}

// ---------------- GEMM1: emb = relu(bagsbf @ W_enc + b_enc) -----------------
// (R10/R13 proven) 128x128 block, 4 warps (2x2) of 64x64, K-step 64, 2-stage,
// ldmatrix fragments, 2 CTAs/SM.
#define LDK 72
#define G1_TILE (128 * LDK)
#define G1_STAGE (2 * G1_TILE)
#define G1_SMEM (2 * G1_STAGE * 2)   // 73728 bytes

__device__ __forceinline__ void g1_stage(__nv_bfloat16* sm, int slot, int kb,
                                         int bm, int bn, int tid) {
    __nv_bfloat16* As = sm + slot * G1_STAGE;
    __nv_bfloat16* Bs = As + G1_TILE;
#pragma unroll
    for (int j = 0; j < 8; j++) {
        int p = tid + j * 128;
        int r = p >> 3, ch = p & 7;
        cp16(&As[r * LDK + ch * 8], &g_bagsbf[(size_t)(bm + r) * FF + kb + ch * 8]);
        cp16(&Bs[r * LDK + ch * 8], &g_WencT[(size_t)(bn + r) * FF + kb + ch * 8]);
    }
}

__global__ __launch_bounds__(128, 2)
void gemm1_kernel(const float* __restrict__ bias) {
    extern __shared__ __nv_bfloat16 sm[];
    __shared__ float s_bias[128];

    const int tid = threadIdx.x, wid = tid >> 5, lane = tid & 31;
    const int wm = wid >> 1, wn = wid & 1, g = lane >> 2, tg = lane & 3;
    const int lr = lane & 7, lm = lane >> 3;
    const int bm = blockIdx.y * 128, bn = blockIdx.x * 128;
    const uint32_t smb = s2u(sm);

    s_bias[tid] = bias[bn + tid];

    const int a_rb = wm * 64 + lr + ((lm & 1) << 3);
    const int a_kc = (lm >> 1) << 3;
    const int b_rb = wn * 64 + lr + ((lm >> 1) << 3);
    const int b_kc = (lm & 1) << 3;

    float acc[4][8][4];
#pragma unroll
    for (int mt = 0; mt < 4; mt++)
#pragma unroll
        for (int nt = 0; nt < 8; nt++)
#pragma unroll
            for (int i = 0; i < 4; i++) acc[mt][nt][i] = 0.f;

#pragma unroll
    for (int s = 0; s < 2; s++) {
        g1_stage(sm, s, s * 64, bm, bn, tid);
        CP_COMMIT();
    }

    for (int c = 0; c < 16; c++) {                 // 16 chunks of K=64
        asm volatile("cp.async.wait_group 1;" ::: "memory");
        __syncthreads();
        const uint32_t sA = smb + (uint32_t)(c & 1) * G1_STAGE * 2;
        const uint32_t sB = sA + G1_TILE * 2;
#pragma unroll
        for (int kk = 0; kk < 64; kk += 16) {
            uint32_t afrag[4][4], bfrag[8][2];
#pragma unroll
            for (int mt = 0; mt < 4; mt++)
                ldsm4(afrag[mt], sA + ((a_rb + mt * 16) * LDK + kk + a_kc) * 2);
#pragma unroll
            for (int np = 0; np < 4; np++) {
                uint32_t t[4];
                ldsm4(t, sB + ((b_rb + np * 16) * LDK + kk + b_kc) * 2);
                bfrag[2 * np][0] = t[0]; bfrag[2 * np][1] = t[1];
                bfrag[2 * np + 1][0] = t[2]; bfrag[2 * np + 1][1] = t[3];
            }
#pragma unroll
            for (int mt = 0; mt < 4; mt++)
#pragma unroll
                for (int nt = 0; nt < 8; nt++)
                    mma_bf16(acc[mt][nt], afrag[mt], bfrag[nt]);
        }
        __syncthreads();
        if (c + 2 < 16) g1_stage(sm, c & 1, (c + 2) * 64, bm, bn, tid);
        CP_COMMIT();
    }

    // epilogue: bias + relu -> bf16
#pragma unroll
    for (int mt = 0; mt < 4; mt++) {
#pragma unroll
        for (int nt = 0; nt < 8; nt++) {
            int row0 = bm + wm * 64 + mt * 16 + g;
            int col = wn * 64 + nt * 8 + 2 * tg;
            float b0 = s_bias[col], b1 = s_bias[col + 1];
            float x0 = fmaxf(acc[mt][nt][0] + b0, 0.f);
            float x1 = fmaxf(acc[mt][nt][1] + b1, 0.f);
            float x2 = fmaxf(acc[mt][nt][2] + b0, 0.f);
            float x3 = fmaxf(acc[mt][nt][3] + b1, 0.f);
            *reinterpret_cast<__nv_bfloat162*>(&g_emb[(size_t)row0 * ZZ + bn + col]) =
                __float22bfloat162_rn(make_float2(x0, x1));
            *reinterpret_cast<__nv_bfloat162*>(&g_emb[(size_t)(row0 + 8) * ZZ + bn + col]) =
                __float22bfloat162_rn(make_float2(x2, x3));
        }
    }
}

// ---------------- fused u/v GEMM + gated + attention logits -----------------
// 128x128 block, 512 threads, 16 warps (4m x 4n) of 32x32 DUAL tiles,
// K-step 32, **4 slots + single barrier per chunk** (stage target (ks+3)%4 is
// the slot consumed at ks-1; the top-of-loop barrier orders compute(ks-1)
// before the overwrite). Commit every iteration keeps wait_group counts exact.
#define LDA 40
#define FU_TILE (128 * LDA)
#define FU_SLOT (3 * FU_TILE)
#define FU_SMEM (4 * FU_SLOT * 2)   // 122880 bytes

__device__ __forceinline__ void fu_stage(__nv_bfloat16* sm, int s, int bm,
                                         int bn, int kb, int tid) {
    __nv_bfloat16* As = sm + s * FU_SLOT;
    __nv_bfloat16* Bu = As + FU_TILE;
    __nv_bfloat16* Bv = Bu + FU_TILE;
    int r = tid >> 2, ch = tid & 3;
    cp16(&As[r * LDA + ch * 8], &g_emb[(size_t)(bm + r) * ZZ + kb + ch * 8]);
    cp16(&Bu[r * LDA + ch * 8], &g_WuT[(size_t)(bn + r) * ZZ + kb + ch * 8]);
    cp16(&Bv[r * LDA + ch * 8], &g_WvT[(size_t)(bn + r) * ZZ + kb + ch * 8]);
}

__global__ __launch_bounds__(512, 1)
void fused_uv_kernel(const float* __restrict__ bu_g,
                     const float* __restrict__ bv_g,
                     const float* __restrict__ Wa_g) {
    extern __shared__ __nv_bfloat16 sm[];
    __shared__ float sBu[128], sBv[128], sWa[CC * 128];

    const int tid = threadIdx.x, wid = tid >> 5, lane = tid & 31;
    const int wm = wid >> 2, wn = wid & 3, g = lane >> 2, tg = lane & 3;
    const int lr = lane & 7, lm = lane >> 3;
    const int bm = blockIdx.y * 128, bn = blockIdx.x * 128;
    const uint32_t smb = s2u(sm);

    if (tid < 128) {
        sBu[tid] = bu_g[bn + tid];
        sBv[tid] = bv_g[bn + tid];
    }
    sWa[tid] = Wa_g[(tid >> 7) * ZZ + bn + (tid & 127)];

    const int a_rb = wm * 32 + lr + ((lm & 1) << 3);
    const int a_kc = (lm >> 1) << 3;
    const int b_rb = wn * 32 + lr + ((lm >> 1) << 3);
    const int b_kc = (lm & 1) << 3;

    float accu[2][4][4], accv[2][4][4];
#pragma unroll
    for (int mt = 0; mt < 2; mt++)
#pragma unroll
        for (int nt = 0; nt < 4; nt++)
#pragma unroll
            for (int i = 0; i < 4; i++) { accu[mt][nt][i] = 0.f; accv[mt][nt][i] = 0.f; }

#pragma unroll
    for (int s = 0; s < 3; s++) {       // chunks 0..2 -> slots 0..2
        fu_stage(sm, s, bm, bn, s * 32, tid);
        CP_COMMIT();
    }

    for (int ks = 0; ks < 16; ks++) {
        asm volatile("cp.async.wait_group 2;" ::: "memory");  // chunk ks ready
        __syncthreads();                 // compute(ks-1) done -> safe to overwrite
        if (ks + 3 < 16) fu_stage(sm, (ks + 3) & 3, bm, bn, (ks + 3) * 32, tid);
        CP_COMMIT();                     // unconditional: keeps group counts exact

        const uint32_t sA = smb + (uint32_t)(ks & 3) * FU_SLOT * 2;
        const uint32_t sU = sA + FU_TILE * 2;
        const uint32_t sV = sU + FU_TILE * 2;
#pragma unroll
        for (int kk = 0; kk < 32; kk += 16) {
            uint32_t a[2][4], bu[4][2], bv[4][2];
#pragma unroll
            for (int mt = 0; mt < 2; mt++)
                ldsm4(a[mt], sA + ((a_rb + mt * 16) * LDA + kk + a_kc) * 2);
#pragma unroll
            for (int np = 0; np < 2; np++) {
                uint32_t t[4];
                ldsm4(t, sU + ((b_rb + np * 16) * LDA + kk + b_kc) * 2);
                bu[2 * np][0] = t[0]; bu[2 * np][1] = t[1];
                bu[2 * np + 1][0] = t[2]; bu[2 * np + 1][1] = t[3];
                ldsm4(t, sV + ((b_rb + np * 16) * LDA + kk + b_kc) * 2);
                bv[2 * np][0] = t[0]; bv[2 * np][1] = t[1];
                bv[2 * np + 1][0] = t[2]; bv[2 * np + 1][1] = t[3];
            }
#pragma unroll
            for (int mt = 0; mt < 2; mt++)
#pragma unroll
                for (int nt = 0; nt < 4; nt++) {
                    mma_bf16(accu[mt][nt], a[mt], bu[nt]);
                    mma_bf16(accv[mt][nt], a[mt], bv[nt]);
                }
        }
    }

    // epilogue: gated = sigmoid(u)*tanh(v); per-class dot -> logits
#pragma unroll
    for (int mt = 0; mt < 2; mt++) {
        float p0[CC] = {0.f, 0.f, 0.f, 0.f};
        float p1[CC] = {0.f, 0.f, 0.f, 0.f};
#pragma unroll
        for (int nt = 0; nt < 4; nt++) {
            int zl = wn * 32 + nt * 8 + 2 * tg;
            float bu0 = sBu[zl], bu1 = sBu[zl + 1];
            float bv0 = sBv[zl], bv1 = sBv[zl + 1];
            float u00 = 0.5f * tanh_ap(0.5f * (accu[mt][nt][0] + bu0)) + 0.5f;
            float u01 = 0.5f * tanh_ap(0.5f * (accu[mt][nt][1] + bu1)) + 0.5f;
            float u10 = 0.5f * tanh_ap(0.5f * (accu[mt][nt][2] + bu0)) + 0.5f;
            float u11 = 0.5f * tanh_ap(0.5f * (accu[mt][nt][3] + bu1)) + 0.5f;
            float g00 = u00 * tanh_ap(accv[mt][nt][0] + bv0);
            float g01 = u01 * tanh_ap(accv[mt][nt][1] + bv1);
            float g10 = u10 * tanh_ap(accv[mt][nt][2] + bv0);
            float g11 = u11 * tanh_ap(accv[mt][nt][3] + bv1);
#pragma unroll
            for (int c = 0; c < CC; c++) {
                float wa0 = sWa[c * 128 + zl], wa1 = sWa[c * 128 + zl + 1];
                p0[c] += g00 * wa0 + g01 * wa1;
                p1[c] += g10 * wa0 + g11 * wa1;
            }
        }
#pragma unroll
        for (int c = 0; c < CC; c++) {
            p0[c] += __shfl_xor_sync(0xffffffffu, p0[c], 1);
            p0[c] += __shfl_xor_sync(0xffffffffu, p0[c], 2);
            p1[c] += __shfl_xor_sync(0xffffffffu, p1[c], 1);
            p1[c] += __shfl_xor_sync(0xffffffffu, p1[c], 2);
        }
        if (tg == 0) {
            int gr0 = bm + wm * 32 + mt * 16 + g;
            int gr1 = gr0 + 8;
            int b0i = gr0 / NN, n0i = gr0 - b0i * NN;
            int b1i = gr1 / NN, n1i = gr1 - b1i * NN;
#pragma unroll
            for (int c = 0; c < CC; c++) {
                atomicAdd(&g_logits[(b0i * CC + c) * NN + n0i], p0[c]);
                atomicAdd(&g_logits[(b1i * CC + c) * NN + n1i], p1[c]);
            }
        }
    }
}

// ---------------- softmax over N per (b,c) ----------------
__global__ __launch_bounds__(256) void softmax_kernel() {
    const int bc = blockIdx.x;
    const float* l = &g_logits[(size_t)bc * NN];
    float* a = &g_attn[(size_t)bc * NN];
    const int t = threadIdx.x;
    __shared__ float red[256];

    float m = -INFINITY;
    for (int n = t; n < NN; n += 256) m = fmaxf(m, l[n]);
    red[t] = m;
    __syncthreads();
    for (int s = 128; s > 0; s >>= 1) {
        if (t < s) red[t] = fmaxf(red[t], red[t + s]);
        __syncthreads();
    }
    m = red[0];
    __syncthreads();
    float sum = 0.f;
    for (int n = t; n < NN; n += 256) {
        float e = expf(l[n] - m);
        a[n] = e;
        sum += e;
    }
    red[t] = sum;
    __syncthreads();
    for (int s = 128; s > 0; s >>= 1) {
        if (t < s) red[t] += red[t + s];
        __syncthreads();
    }
    float inv = 1.f / red[0];
    for (int n = t; n < NN; n += 256) a[n] *= inv;
}

// ---------------- reps = sum_n attn[b,c,n] * emb[b,n,z] ----------------
#define NSPLIT 100   // 10000 / 100 = 100
__global__ __launch_bounds__(256) void reps_kernel() {
    const int ns = blockIdx.x;
    const int b = blockIdx.y;
    const int z = 2 * threadIdx.x;
    const int n0 = ns * (NN / NSPLIT), n1 = n0 + (NN / NSPLIT);
    const __nv_bfloat16* e = &g_emb[(size_t)b * NN * ZZ];

    float a0[CC] = {0.f, 0.f, 0.f, 0.f};
    float a1[CC] = {0.f, 0.f, 0.f, 0.f};
#pragma unroll 2
    for (int n = n0; n < n1; n++) {
        __nv_bfloat162 ev = *reinterpret_cast<const __nv_bfloat162*>(&e[(size_t)n * ZZ + z]);
        float2 ef = __bfloat1622float2(ev);
#pragma unroll
        for (int c = 0; c < CC; c++) {
            float at = g_attn[(b * CC + c) * NN + n];
            a0[c] += at * ef.x;
            a1[c] += at * ef.y;
        }
    }
#pragma unroll
    for (int c = 0; c < CC; c++) {
        atomicAdd(&g_reps[(b * CC + c) * ZZ + z], a0[c]);
        atomicAdd(&g_reps[(b * CC + c) * ZZ + z + 1], a1[c]);
    }
}

// ---------------- scores ----------------
__global__ __launch_bounds__(1024)
void scores_kernel(const float* __restrict__ W_cls,
                   const float* __restrict__ b_cls, float* __restrict__ out) {
    const int w = threadIdx.x >> 5, lane = threadIdx.x & 31;
    const int b = w >> 2, c = w & 3;
    float s = 0.f;
    for (int z = lane; z < ZZ; z += 32)
        s += g_reps[(b * CC + c) * ZZ + z] * W_cls[c * ZZ + z];
#pragma unroll
    for (int o = 16; o > 0; o >>= 1) s += __shfl_xor_sync(0xffffffffu, s, o);
    if (lane == 0) out[b * CC + c] = s + b_cls[c];
}

// ---------------- launch ----------------
extern "C" void kernel_launch(void* const* d_in, const int* in_sizes, int n_in,
                              void* d_out, int out_size) {
    const float* bags   = (const float*)d_in[0];
    const float* W_enc  = (const float*)d_in[1];
    const float* b_enc  = (const float*)d_in[2];
    const float* W_u    = (const float*)d_in[3];
    const float* b_u    = (const float*)d_in[4];
    const float* W_v    = (const float*)d_in[5];
    const float* b_v    = (const float*)d_in[6];
    const float* W_attn = (const float*)d_in[7];
    const float* b_attn = (const float*)d_in[8];
    const float* W_cls  = (const float*)d_in[9];
    const float* b_cls  = (const float*)d_in[10];
    float* out = (float*)d_out;

    cudaFuncSetAttribute(gemm1_kernel, cudaFuncAttributeMaxDynamicSharedMemorySize, G1_SMEM);
    cudaFuncSetAttribute(fused_uv_kernel, cudaFuncAttributeMaxDynamicSharedMemorySize, FU_SMEM);

    // [1] bags fp32 -> bf16
    convert_bags_kernel<<<40000, 256>>>(bags);
    // [2] merged prep: weight transposes + logits/reps init
    prep_kernel<<<(FF * ZZ + 255) / 256, 256>>>(W_enc, W_u, W_v, b_attn);
    // [3] encoder GEMM (proven)
    gemm1_kernel<<<dim3(ZZ / 128, ROWS / 128), 128, G1_SMEM>>>(b_enc);
    // [4] fused u/v GEMM (4-slot single-barrier pipeline) -> profiled
    fused_uv_kernel<<<dim3(ZZ / 128, ROWS / 128), 512, FU_SMEM>>>(b_u, b_v, W_attn);

    softmax_kernel<<<BB * CC, 256>>>();
    reps_kernel<<<dim3(NSPLIT, BB), 256>>>();
    scores_kernel<<<1, 1024>>>(W_cls, b_cls, out);
}

// round 16
// speedup vs baseline: 1.0482x; 1.0370x over previous
#include <cuda_runtime.h>
#include <cuda_bf16.h>
#include <math.h>
#include <stdint.h>

#define BB 8
#define NN 10000
#define FF 1024
#define ZZ 512
#define CC 4
#define ROWS (BB * NN)   // 80000 = 625 * 128

// ---------------- scratch (no allocations allowed) ----------------
__device__ __nv_bfloat16 g_bagsbf[(size_t)ROWS * FF];
__device__ __nv_bfloat16 g_emb[(size_t)ROWS * ZZ];
__device__ __nv_bfloat16 g_WencT[(size_t)ZZ * FF];  // [n][k]
__device__ __nv_bfloat16 g_WuT[(size_t)ZZ * ZZ];    // [n][k]
__device__ __nv_bfloat16 g_WvT[(size_t)ZZ * ZZ];    // [n][k]
__device__ float g_logits[BB * CC * NN];
__device__ float g_attn[BB * CC * NN];
__device__ float g_reps[BB * CC * ZZ];

// ---------------- helpers ----------------
__device__ __forceinline__ uint32_t s2u(const void* p) {
    uint32_t a;
    asm("{ .reg .u64 t; cvta.to.shared.u64 t, %1; cvt.u32.u64 %0, t; }"
        : "=r"(a) : "l"(p));
    return a;
}

__device__ __forceinline__ void mma_bf16(float d[4], const uint32_t a[4],
                                         const uint32_t b[2]) {
    asm volatile(
        "mma.sync.aligned.m16n8k16.row.col.f32.bf16.bf16.f32 "
        "{%0,%1,%2,%3}, {%4,%5,%6,%7}, {%8,%9}, {%0,%1,%2,%3};"
        : "+f"(d[0]), "+f"(d[1]), "+f"(d[2]), "+f"(d[3])
        : "r"(a[0]), "r"(a[1]), "r"(a[2]), "r"(a[3]), "r"(b[0]), "r"(b[1]));
}

__device__ __forceinline__ void ldsm4(uint32_t* r, uint32_t addr) {
    asm volatile("ldmatrix.sync.aligned.m8n8.x4.shared.b16 {%0,%1,%2,%3}, [%4];"
                 : "=r"(r[0]), "=r"(r[1]), "=r"(r[2]), "=r"(r[3]) : "r"(addr));
}

__device__ __forceinline__ void cp16(void* dst, const void* src) {
    uint32_t d = (uint32_t)__cvta_generic_to_shared(dst);
    asm volatile("cp.async.cg.shared.global [%0], [%1], 16;" ::"r"(d), "l"(src));
}
#define CP_COMMIT() asm volatile("cp.async.commit_group;" ::: "memory")

__device__ __forceinline__ float tanh_ap(float x) {
    float r;
    asm("tanh.approx.f32 %0, %1;" : "=f"(r) : "f"(x));
    return r;
}

// ---------------- prep kernels ----------------
__global__ void convert_bags_kernel(const float* __restrict__ in) {
    size_t i = ((size_t)blockIdx.x * 256 + threadIdx.x) * 8;
#pragma unroll
    for (int j = 0; j < 2; j++) {
        float4 v = *reinterpret_cast<const float4*>(in + i + 4 * j);
        __nv_bfloat162 lo = __float22bfloat162_rn(make_float2(v.x, v.y));
        __nv_bfloat162 hi = __float22bfloat162_rn(make_float2(v.z, v.w));
        uint2 u;
        u.x = *reinterpret_cast<uint32_t*>(&lo);
        u.y = *reinterpret_cast<uint32_t*>(&hi);
        *reinterpret_cast<uint2*>(&g_bagsbf[i + 4 * j]) = u;
    }
}

__global__ void prep_kernel(const float* __restrict__ We,
                            const float* __restrict__ Wu,
                            const float* __restrict__ Wv,
                            const float* __restrict__ b_attn) {
    int i = blockIdx.x * 256 + threadIdx.x;
    if (i < FF * ZZ) {
        int k = i / ZZ, n = i - k * ZZ;
        g_WencT[(size_t)n * FF + k] = __float2bfloat16(We[i]);
    }
    if (i < ZZ * ZZ) {
        int k = i / ZZ, n = i - k * ZZ;
        g_WuT[(size_t)n * ZZ + k] = __float2bfloat16(Wu[i]);
        g_WvT[(size_t)n * ZZ + k] = __float2bfloat16(Wv[i]);
    }
    if (i < BB * CC * NN) g_logits[i] = b_attn[(i / NN) & 3];
    if (i < BB * CC * ZZ) g_reps[i] = 0.f;
}

// ---------------- GEMM1: emb = relu(bagsbf @ W_enc + b_enc) -----------------
// (proven) 128x128 block, 4 warps (2x2) of 64x64, K-step 64, 2-stage,
// ldmatrix fragments, 2 CTAs/SM.
#define LDK 72
#define G1_TILE (128 * LDK)
#define G1_STAGE (2 * G1_TILE)
#define G1_SMEM (2 * G1_STAGE * 2)   // 73728 bytes

__device__ __forceinline__ void g1_stage(__nv_bfloat16* sm, int slot, int kb,
                                         int bm, int bn, int tid) {
    __nv_bfloat16* As = sm + slot * G1_STAGE;
    __nv_bfloat16* Bs = As + G1_TILE;
#pragma unroll
    for (int j = 0; j < 8; j++) {
        int p = tid + j * 128;
        int r = p >> 3, ch = p & 7;
        cp16(&As[r * LDK + ch * 8], &g_bagsbf[(size_t)(bm + r) * FF + kb + ch * 8]);
        cp16(&Bs[r * LDK + ch * 8], &g_WencT[(size_t)(bn + r) * FF + kb + ch * 8]);
    }
}

__global__ __launch_bounds__(128, 2)
void gemm1_kernel(const float* __restrict__ bias) {
    extern __shared__ __nv_bfloat16 sm[];
    __shared__ float s_bias[128];

    const int tid = threadIdx.x, wid = tid >> 5, lane = tid & 31;
    const int wm = wid >> 1, wn = wid & 1, g = lane >> 2, tg = lane & 3;
    const int lr = lane & 7, lm = lane >> 3;
    const int bm = blockIdx.y * 128, bn = blockIdx.x * 128;
    const uint32_t smb = s2u(sm);

    s_bias[tid] = bias[bn + tid];

    const int a_rb = wm * 64 + lr + ((lm & 1) << 3);
    const int a_kc = (lm >> 1) << 3;
    const int b_rb = wn * 64 + lr + ((lm >> 1) << 3);
    const int b_kc = (lm & 1) << 3;

    float acc[4][8][4];
#pragma unroll
    for (int mt = 0; mt < 4; mt++)
#pragma unroll
        for (int nt = 0; nt < 8; nt++)
#pragma unroll
            for (int i = 0; i < 4; i++) acc[mt][nt][i] = 0.f;

#pragma unroll
    for (int s = 0; s < 2; s++) {
        g1_stage(sm, s, s * 64, bm, bn, tid);
        CP_COMMIT();
    }

    for (int c = 0; c < 16; c++) {                 // 16 chunks of K=64
        asm volatile("cp.async.wait_group 1;" ::: "memory");
        __syncthreads();
        const uint32_t sA = smb + (uint32_t)(c & 1) * G1_STAGE * 2;
        const uint32_t sB = sA + G1_TILE * 2;
#pragma unroll
        for (int kk = 0; kk < 64; kk += 16) {
            uint32_t afrag[4][4], bfrag[8][2];
#pragma unroll
            for (int mt = 0; mt < 4; mt++)
                ldsm4(afrag[mt], sA + ((a_rb + mt * 16) * LDK + kk + a_kc) * 2);
#pragma unroll
            for (int np = 0; np < 4; np++) {
                uint32_t t[4];
                ldsm4(t, sB + ((b_rb + np * 16) * LDK + kk + b_kc) * 2);
                bfrag[2 * np][0] = t[0]; bfrag[2 * np][1] = t[1];
                bfrag[2 * np + 1][0] = t[2]; bfrag[2 * np + 1][1] = t[3];
            }
#pragma unroll
            for (int mt = 0; mt < 4; mt++)
#pragma unroll
                for (int nt = 0; nt < 8; nt++)
                    mma_bf16(acc[mt][nt], afrag[mt], bfrag[nt]);
        }
        __syncthreads();
        if (c + 2 < 16) g1_stage(sm, c & 1, (c + 2) * 64, bm, bn, tid);
        CP_COMMIT();
    }

    // epilogue: bias + relu -> bf16
#pragma unroll
    for (int mt = 0; mt < 4; mt++) {
#pragma unroll
        for (int nt = 0; nt < 8; nt++) {
            int row0 = bm + wm * 64 + mt * 16 + g;
            int col = wn * 64 + nt * 8 + 2 * tg;
            float b0 = s_bias[col], b1 = s_bias[col + 1];
            float x0 = fmaxf(acc[mt][nt][0] + b0, 0.f);
            float x1 = fmaxf(acc[mt][nt][1] + b1, 0.f);
            float x2 = fmaxf(acc[mt][nt][2] + b0, 0.f);
            float x3 = fmaxf(acc[mt][nt][3] + b1, 0.f);
            *reinterpret_cast<__nv_bfloat162*>(&g_emb[(size_t)row0 * ZZ + bn + col]) =
                __float22bfloat162_rn(make_float2(x0, x1));
            *reinterpret_cast<__nv_bfloat162*>(&g_emb[(size_t)(row0 + 8) * ZZ + bn + col]) =
                __float22bfloat162_rn(make_float2(x2, x3));
        }
    }
}

// ---------------- fused u/v GEMM + gated + attention logits -----------------
// (R13 proven form) 128x128 block, 512 threads, 16 warps (4m x 4n) of 32x32
// DUAL tiles, K-step 32, 3 stages, two barriers per chunk, ldmatrix fragments.
#define LDA 40
#define FU_TILE (128 * LDA)
#define FU_STAGE (3 * FU_TILE)
#define FU_SMEM (3 * FU_STAGE * 2)   // 92160 bytes

__device__ __forceinline__ void fu_stage(__nv_bfloat16* sm, int s, int bm,
                                         int bn, int kb, int tid) {
    __nv_bfloat16* As = sm + s * FU_STAGE;
    __nv_bfloat16* Bu = As + FU_TILE;
    __nv_bfloat16* Bv = Bu + FU_TILE;
    int r = tid >> 2, ch = tid & 3;
    cp16(&As[r * LDA + ch * 8], &g_emb[(size_t)(bm + r) * ZZ + kb + ch * 8]);
    cp16(&Bu[r * LDA + ch * 8], &g_WuT[(size_t)(bn + r) * ZZ + kb + ch * 8]);
    cp16(&Bv[r * LDA + ch * 8], &g_WvT[(size_t)(bn + r) * ZZ + kb + ch * 8]);
}

__global__ __launch_bounds__(512, 1)
void fused_uv_kernel(const float* __restrict__ bu_g,
                     const float* __restrict__ bv_g,
                     const float* __restrict__ Wa_g) {
    extern __shared__ __nv_bfloat16 sm[];
    __shared__ float sBu[128], sBv[128], sWa[CC * 128];

    const int tid = threadIdx.x, wid = tid >> 5, lane = tid & 31;
    const int wm = wid >> 2, wn = wid & 3, g = lane >> 2, tg = lane & 3;
    const int lr = lane & 7, lm = lane >> 3;
    const int bm = blockIdx.y * 128, bn = blockIdx.x * 128;
    const uint32_t smb = s2u(sm);

    if (tid < 128) {
        sBu[tid] = bu_g[bn + tid];
        sBv[tid] = bv_g[bn + tid];
    }
    sWa[tid] = Wa_g[(tid >> 7) * ZZ + bn + (tid & 127)];

    const int a_rb = wm * 32 + lr + ((lm & 1) << 3);
    const int a_kc = (lm >> 1) << 3;
    const int b_rb = wn * 32 + lr + ((lm >> 1) << 3);
    const int b_kc = (lm & 1) << 3;

    float accu[2][4][4], accv[2][4][4];
#pragma unroll
    for (int mt = 0; mt < 2; mt++)
#pragma unroll
        for (int nt = 0; nt < 4; nt++)
#pragma unroll
            for (int i = 0; i < 4; i++) { accu[mt][nt][i] = 0.f; accv[mt][nt][i] = 0.f; }

#pragma unroll
    for (int s = 0; s < 3; s++) {
        fu_stage(sm, s, bm, bn, s * 32, tid);
        CP_COMMIT();
    }

    for (int ks = 0; ks < 16; ks++) {
        asm volatile("cp.async.wait_group 2;" ::: "memory");
        __syncthreads();
        const uint32_t sA = smb + (uint32_t)(ks % 3) * FU_STAGE * 2;
        const uint32_t sU = sA + FU_TILE * 2;
        const uint32_t sV = sU + FU_TILE * 2;
#pragma unroll
        for (int kk = 0; kk < 32; kk += 16) {
            uint32_t a[2][4], bu[4][2], bv[4][2];
#pragma unroll
            for (int mt = 0; mt < 2; mt++)
                ldsm4(a[mt], sA + ((a_rb + mt * 16) * LDA + kk + a_kc) * 2);
#pragma unroll
            for (int np = 0; np < 2; np++) {
                uint32_t t[4];
                ldsm4(t, sU + ((b_rb + np * 16) * LDA + kk + b_kc) * 2);
                bu[2 * np][0] = t[0]; bu[2 * np][1] = t[1];
                bu[2 * np + 1][0] = t[2]; bu[2 * np + 1][1] = t[3];
                ldsm4(t, sV + ((b_rb + np * 16) * LDA + kk + b_kc) * 2);
                bv[2 * np][0] = t[0]; bv[2 * np][1] = t[1];
                bv[2 * np + 1][0] = t[2]; bv[2 * np + 1][1] = t[3];
            }
#pragma unroll
            for (int mt = 0; mt < 2; mt++)
#pragma unroll
                for (int nt = 0; nt < 4; nt++) {
                    mma_bf16(accu[mt][nt], a[mt], bu[nt]);
                    mma_bf16(accv[mt][nt], a[mt], bv[nt]);
                }
        }
        __syncthreads();
        if (ks + 3 < 16) fu_stage(sm, ks % 3, bm, bn, (ks + 3) * 32, tid);
        CP_COMMIT();
    }

    // epilogue: gated = sigmoid(u)*tanh(v); per-class dot -> logits
#pragma unroll
    for (int mt = 0; mt < 2; mt++) {
        float p0[CC] = {0.f, 0.f, 0.f, 0.f};
        float p1[CC] = {0.f, 0.f, 0.f, 0.f};
#pragma unroll
        for (int nt = 0; nt < 4; nt++) {
            int zl = wn * 32 + nt * 8 + 2 * tg;
            float bu0 = sBu[zl], bu1 = sBu[zl + 1];
            float bv0 = sBv[zl], bv1 = sBv[zl + 1];
            float u00 = 0.5f * tanh_ap(0.5f * (accu[mt][nt][0] + bu0)) + 0.5f;
            float u01 = 0.5f * tanh_ap(0.5f * (accu[mt][nt][1] + bu1)) + 0.5f;
            float u10 = 0.5f * tanh_ap(0.5f * (accu[mt][nt][2] + bu0)) + 0.5f;
            float u11 = 0.5f * tanh_ap(0.5f * (accu[mt][nt][3] + bu1)) + 0.5f;
            float g00 = u00 * tanh_ap(accv[mt][nt][0] + bv0);
            float g01 = u01 * tanh_ap(accv[mt][nt][1] + bv1);
            float g10 = u10 * tanh_ap(accv[mt][nt][2] + bv0);
            float g11 = u11 * tanh_ap(accv[mt][nt][3] + bv1);
#pragma unroll
            for (int c = 0; c < CC; c++) {
                float wa0 = sWa[c * 128 + zl], wa1 = sWa[c * 128 + zl + 1];
                p0[c] += g00 * wa0 + g01 * wa1;
                p1[c] += g10 * wa0 + g11 * wa1;
            }
        }
#pragma unroll
        for (int c = 0; c < CC; c++) {
            p0[c] += __shfl_xor_sync(0xffffffffu, p0[c], 1);
            p0[c] += __shfl_xor_sync(0xffffffffu, p0[c], 2);
            p1[c] += __shfl_xor_sync(0xffffffffu, p1[c], 1);
            p1[c] += __shfl_xor_sync(0xffffffffu, p1[c], 2);
        }
        if (tg == 0) {
            int gr0 = bm + wm * 32 + mt * 16 + g;
            int gr1 = gr0 + 8;
            int b0i = gr0 / NN, n0i = gr0 - b0i * NN;
            int b1i = gr1 / NN, n1i = gr1 - b1i * NN;
#pragma unroll
            for (int c = 0; c < CC; c++) {
                atomicAdd(&g_logits[(b0i * CC + c) * NN + n0i], p0[c]);
                atomicAdd(&g_logits[(b1i * CC + c) * NN + n1i], p1[c]);
            }
        }
    }
}

// ---------------- softmax over N per (b,c) ----------------
__global__ __launch_bounds__(256) void softmax_kernel() {
    const int bc = blockIdx.x;
    const float* l = &g_logits[(size_t)bc * NN];
    float* a = &g_attn[(size_t)bc * NN];
    const int t = threadIdx.x;
    __shared__ float red[256];

    float m = -INFINITY;
    for (int n = t; n < NN; n += 256) m = fmaxf(m, l[n]);
    red[t] = m;
    __syncthreads();
    for (int s = 128; s > 0; s >>= 1) {
        if (t < s) red[t] = fmaxf(red[t], red[t + s]);
        __syncthreads();
    }
    m = red[0];
    __syncthreads();
    float sum = 0.f;
    for (int n = t; n < NN; n += 256) {
        float e = expf(l[n] - m);
        a[n] = e;
        sum += e;
    }
    red[t] = sum;
    __syncthreads();
    for (int s = 128; s > 0; s >>= 1) {
        if (t < s) red[t] += red[t + s];
        __syncthreads();
    }
    float inv = 1.f / red[0];
    for (int n = t; n < NN; n += 256) a[n] *= inv;
}

// ---------------- reps = sum_n attn[b,c,n] * emb[b,n,z] ----------------
#define NSPLIT 100   // 10000 / 100 = 100
__global__ __launch_bounds__(256) void reps_kernel() {
    const int ns = blockIdx.x;
    const int b = blockIdx.y;
    const int z = 2 * threadIdx.x;
    const int n0 = ns * (NN / NSPLIT), n1 = n0 + (NN / NSPLIT);
    const __nv_bfloat16* e = &g_emb[(size_t)b * NN * ZZ];

    float a0[CC] = {0.f, 0.f, 0.f, 0.f};
    float a1[CC] = {0.f, 0.f, 0.f, 0.f};
#pragma unroll 2
    for (int n = n0; n < n1; n++) {
        __nv_bfloat162 ev = *reinterpret_cast<const __nv_bfloat162*>(&e[(size_t)n * ZZ + z]);
        float2 ef = __bfloat1622float2(ev);
#pragma unroll
        for (int c = 0; c < CC; c++) {
            float at = g_attn[(b * CC + c) * NN + n];
            a0[c] += at * ef.x;
            a1[c] += at * ef.y;
        }
    }
#pragma unroll
    for (int c = 0; c < CC; c++) {
        atomicAdd(&g_reps[(b * CC + c) * ZZ + z], a0[c]);
        atomicAdd(&g_reps[(b * CC + c) * ZZ + z + 1], a1[c]);
    }
}

// ---------------- scores ----------------
__global__ __launch_bounds__(1024)
void scores_kernel(const float* __restrict__ W_cls,
                   const float* __restrict__ b_cls, float* __restrict__ out) {
    const int w = threadIdx.x >> 5, lane = threadIdx.x & 31;
    const int b = w >> 2, c = w & 3;
    float s = 0.f;
    for (int z = lane; z < ZZ; z += 32)
        s += g_reps[(b * CC + c) * ZZ + z] * W_cls[c * ZZ + z];
#pragma unroll
    for (int o = 16; o > 0; o >>= 1) s += __shfl_xor_sync(0xffffffffu, s, o);
    if (lane == 0) out[b * CC + c] = s + b_cls[c];
}

// ---------------- launch ----------------
extern "C" void kernel_launch(void* const* d_in, const int* in_sizes, int n_in,
                              void* d_out, int out_size) {
    const float* bags   = (const float*)d_in[0];
    const float* W_enc  = (const float*)d_in[1];
    const float* b_enc  = (const float*)d_in[2];
    const float* W_u    = (const float*)d_in[3];
    const float* b_u    = (const float*)d_in[4];
    const float* W_v    = (const float*)d_in[5];
    const float* b_v    = (const float*)d_in[6];
    const float* W_attn = (const float*)d_in[7];
    const float* b_attn = (const float*)d_in[8];
    const float* W_cls  = (const float*)d_in[9];
    const float* b_cls  = (const float*)d_in[10];
    float* out = (float*)d_out;

    cudaFuncSetAttribute(gemm1_kernel, cudaFuncAttributeMaxDynamicSharedMemorySize, G1_SMEM);
    cudaFuncSetAttribute(fused_uv_kernel, cudaFuncAttributeMaxDynamicSharedMemorySize, FU_SMEM);

    // [1] bags fp32 -> bf16
    convert_bags_kernel<<<40000, 256>>>(bags);
    // [2] merged prep: weight transposes + logits/reps init
    prep_kernel<<<(FF * ZZ + 255) / 256, 256>>>(W_enc, W_u, W_v, b_attn);
    // [3] encoder GEMM (proven)
    gemm1_kernel<<<dim3(ZZ / 128, ROWS / 128), 128, G1_SMEM>>>(b_enc);
    // [4] fused u/v GEMM (R13 proven form)
    fused_uv_kernel<<<dim3(ZZ / 128, ROWS / 128), 512, FU_SMEM>>>(b_u, b_v, W_attn);

    softmax_kernel<<<BB * CC, 256>>>();
    reps_kernel<<<dim3(NSPLIT, BB), 256>>>();
    scores_kernel<<<1, 1024>>>(W_cls, b_cls, out);
}